// round 13
// baseline (speedup 1.0000x reference)
#include <cuda_runtime.h>
#include <cuda_fp16.h>
#include <math.h>
#include <stdint.h>

// Problem constants
#define Bn   16
#define Cc   256
#define HWn  4096
#define NHh  4
#define HDd  64
#define CHW  1048576L   // C*HW
#define NSPL 8          // n-split slabs for attention scores

// ---------------- scratch (static __device__ — no allocation allowed) ----------------
__device__ float g_q[16777216];      // (B,256,HW)
__device__ float g_kv[67108864];     // (2B,512,HW)
__device__ float g_attn[16777216];   // (B,256,HW)
__device__ float g_x[16777216];      // residual mid
__device__ float g_y1[16777216];
__device__ float g_y2[16777216];
__device__ float g_S[NSPL*64*64*128];   // score partials [slab][bh][c][dd]
__device__ float g_qn2[NSPL*64*64];
__device__ float g_kn2[NSPL*64*128];
__device__ float g_P[64*64*128];        // gated softmax probs [bh][c][dd]
__device__ float g_Sq[256],  g_Bq[256];
__device__ float g_Skv[512], g_Bkv[512];
__device__ float g_Sf1[256], g_Bf1[256];
// pre-split packed fp16 weight pairs (pairs along k): rows q:0 kv:256 f1:768 o:1024 f2:1280
__device__ unsigned g_Whp[196608];
__device__ unsigned g_Wlp[196608];

// ---------------- fp16 helpers ----------------
__device__ __forceinline__ unsigned pack2h(float x, float y)
{
    __half2 h = __floats2half2_rn(x, y);
    return *reinterpret_cast<unsigned*>(&h);
}
__device__ __forceinline__ void split2h(float x, float y, unsigned &hi, unsigned &lo)
{
    __half2 h = __floats2half2_rn(x, y);
    float rx = x - __low2float(h);
    float ry = y - __high2float(h);
    __half2 l = __floats2half2_rn(rx, ry);
    hi = *reinterpret_cast<unsigned*>(&h);
    lo = *reinterpret_cast<unsigned*>(&l);
}
__device__ __forceinline__ void mma_f16(float* c, const unsigned* a, unsigned b0, unsigned b1)
{
    asm volatile(
        "mma.sync.aligned.m16n8k16.row.col.f32.f16.f16.f32 "
        "{%0,%1,%2,%3},{%4,%5,%6,%7},{%8,%9},{%0,%1,%2,%3};\n"
        : "+f"(c[0]), "+f"(c[1]), "+f"(c[2]), "+f"(c[3])
        : "r"(a[0]), "r"(a[1]), "r"(a[2]), "r"(a[3]), "r"(b0), "r"(b1));
}

// ---------------- weight fold + pre-split: rows 0..1535 ----------------
__global__ void prep_w(const float* __restrict__ qw,  const float* __restrict__ qlw,  const float* __restrict__ qlb,
                       const float* __restrict__ kvw, const float* __restrict__ kvlw, const float* __restrict__ kvlb,
                       const float* __restrict__ f1w, const float* __restrict__ flw,  const float* __restrict__ flb,
                       const float* __restrict__ ow,  const float* __restrict__ f2w)
{
    int row = blockIdx.x;  // 0..1535
    const float *W, *lw = 0, *lb = 0; float *So = 0, *Bo = 0; int o; bool fold;
    if (row < 256)       { W=qw;  lw=qlw;  lb=qlb;  So=g_Sq;  Bo=g_Bq;  o=row;      fold=true; }
    else if (row < 768)  { W=kvw; lw=kvlw; lb=kvlb; So=g_Skv; Bo=g_Bkv; o=row-256;  fold=true; }
    else if (row < 1024) { W=f1w; lw=flw;  lb=flb;  So=g_Sf1; Bo=g_Bf1; o=row-768;  fold=true; }
    else if (row < 1280) { W=ow;  o=row-1024; fold=false; }
    else                 { W=f2w; o=row-1280; fold=false; }
    int c = threadIdx.x;
    float w  = W[o*256 + c];
    float wp = fold ? w * lw[c] : w;
    float bb = fold ? w * lb[c] : 0.f;
    __shared__ float wv[256], r1[256], r2[256];
    wv[c] = wp; r1[c] = wp; r2[c] = bb;
    __syncthreads();
    for (int s = 128; s > 0; s >>= 1) {
        if (c < s) { r1[c] += r1[c+s]; r2[c] += r2[c+s]; }
        __syncthreads();
    }
    if (fold && c == 0) { So[o] = r1[0]; Bo[o] = r2[0]; }
    if (c < 128) {
        unsigned hi, lo;
        split2h(wv[2*c], wv[2*c+1], hi, lo);
        g_Whp[row*128 + c] = hi;
        g_Wlp[row*128 + c] = lo;
    }
}

// ---------------- tensor-core 128x128x256 GEMM, fused LN stats, 2xFP16 ----------------
// out[bz][m][n] = epilogue( sum_c A[m][c] * X[bz][c][n] )
// do_ln: compute per-pixel mu/rstd from the streamed X tile and apply LN-fold epilogue.
__global__ void __launch_bounds__(256) gemm_tc(
    int aoff,
    const float* __restrict__ X0, const float* __restrict__ X1, int split, long sX,
    float* __restrict__ Out, long sOut,
    int do_ln,
    const float* __restrict__ Srow, const float* __restrict__ bias2,
    const float* __restrict__ bias,
    const float* __restrict__ Res, long sRes)
{
    int bz = blockIdx.z;
    const float* X   = (bz < split) ? X0 + (long)bz*sX : X1 + (long)(bz-split)*sX;
    float*       out = Out + (long)bz*sOut;
    const float* res = Res ? Res + (long)bz*sRes : (const float*)0;
    int n0 = blockIdx.x * 128, m0 = blockIdx.y * 128;

    __shared__ unsigned Ahs[16][136], Als[16][136];  // [kp][m] (one 32-k chunk)
    __shared__ unsigned Bhs[16][136];                // [kp][n]
    __shared__ float red1[256], red2[256];
    __shared__ float mu_s[128], rs_s[128];

    int tid  = threadIdx.x;
    int lane = tid & 31, wid = tid >> 5;
    int g = lane >> 2, l4 = lane & 3;
    int wm = wid >> 1, wn = wid & 1;

    int am2 = tid & 127;          // A staging row
    int aq  = tid >> 7;           // 0/1; q = aq + 2*rep
    int bn  = tid & 127;          // B staging column
    int bh2 = tid >> 7;           // 0/1: k half within chunk
    const float* Xc = X + n0 + bn;

    float acc[2][8][4];
    #pragma unroll
    for (int i = 0; i < 2; i++)
        #pragma unroll
        for (int j = 0; j < 8; j++)
            #pragma unroll
            for (int r = 0; r < 4; r++) acc[i][j][r] = 0.f;
    float s1 = 0.f, s2 = 0.f;

    for (int it = 0; it < 8; it++) {
        // ---- stage A (128 x 32) from pre-split packed pairs ----
        #pragma unroll
        for (int rep = 0; rep < 2; rep++) {
            int q = aq + 2*rep;                       // 0..3 (4 kps each)
            long off = (long)(aoff + m0 + am2)*128 + it*16 + q*4;
            uint4 hv = *(const uint4*)&g_Whp[off];
            uint4 lv = *(const uint4*)&g_Wlp[off];
            Ahs[q*4+0][am2]=hv.x; Ahs[q*4+1][am2]=hv.y; Ahs[q*4+2][am2]=hv.z; Ahs[q*4+3][am2]=hv.w;
            Als[q*4+0][am2]=lv.x; Als[q*4+1][am2]=lv.y; Als[q*4+2][am2]=lv.z; Als[q*4+3][am2]=lv.w;
        }
        // ---- stage B (32 x 128): 16 k rows per thread, one column; accumulate stats ----
        {
            int kbase = it*32 + bh2*16;
            float v[16];
            #pragma unroll
            for (int i = 0; i < 16; i++) v[i] = Xc[(long)(kbase + i)*HWn];
            if (do_ln) {
                #pragma unroll
                for (int i = 0; i < 16; i++) { s1 += v[i]; s2 += v[i]*v[i]; }
            }
            #pragma unroll
            for (int i2 = 0; i2 < 8; i2++)
                Bhs[bh2*8 + i2][bn] = pack2h(v[2*i2], v[2*i2+1]);
        }
        __syncthreads();
        // ---- 64 MMAs per chunk ----
        #pragma unroll
        for (int kk = 0; kk < 16; kk += 8) {
            unsigned a_h[2][4], a_l[2][4];
            #pragma unroll
            for (int i = 0; i < 2; i++) {
                int row = wm*32 + i*16 + g;
                a_h[i][0]=Ahs[kk+l4][row];   a_h[i][1]=Ahs[kk+l4][row+8];
                a_h[i][2]=Ahs[kk+l4+4][row]; a_h[i][3]=Ahs[kk+l4+4][row+8];
                a_l[i][0]=Als[kk+l4][row];   a_l[i][1]=Als[kk+l4][row+8];
                a_l[i][2]=Als[kk+l4+4][row]; a_l[i][3]=Als[kk+l4+4][row+8];
            }
            #pragma unroll
            for (int j = 0; j < 8; j++) {
                int col = wn*64 + j*8 + g;
                unsigned bh0=Bhs[kk+l4][col], bh1=Bhs[kk+l4+4][col];
                #pragma unroll
                for (int i = 0; i < 2; i++) {
                    mma_f16(acc[i][j], a_h[i], bh0, bh1);
                    mma_f16(acc[i][j], a_l[i], bh0, bh1);
                }
            }
        }
        __syncthreads();
    }

    // ---- finalize LN stats (2 threads per column) ----
    if (do_ln) {
        red1[tid] = s1; red2[tid] = s2;
        __syncthreads();
        if (tid < 128) {
            float t1 = red1[tid] + red1[tid+128];
            float t2 = red2[tid] + red2[tid+128];
            float m  = t1 * (1.0f/256.0f);
            mu_s[tid] = m;
            rs_s[tid] = rsqrtf(fmaxf(t2*(1.0f/256.0f) - m*m, 0.f) + 1e-6f);
        }
        __syncthreads();
    }

    #pragma unroll
    for (int i = 0; i < 2; i++) {
        #pragma unroll
        for (int h = 0; h < 2; h++) {
            int m = m0 + wm*32 + i*16 + g + h*8;
            float sr = 0.f, b2 = 0.f;
            if (do_ln)    { sr = Srow[m]; b2 = bias2[m]; }
            else if (bias){ b2 = bias[m]; }
            #pragma unroll
            for (int j = 0; j < 8; j++) {
                int nn = wn*64 + j*8 + 2*l4;     // local column 0..127
                int n  = n0 + nn;
                float v0 = acc[i][j][h*2+0], v1 = acc[i][j][h*2+1];
                if (do_ln) {
                    v0 = rs_s[nn  ]*(v0 - mu_s[nn  ]*sr) + b2;
                    v1 = rs_s[nn+1]*(v1 - mu_s[nn+1]*sr) + b2;
                } else {
                    v0 += b2; v1 += b2;
                    if (res) { v0 += res[(long)m*HWn + n]; v1 += res[(long)m*HWn + n + 1]; }
                }
                *(float2*)&out[(long)m*HWn + n] = make_float2(v0, v1);
            }
        }
    }
}

// ---------------- attention A1: raw scores Q*[Ktex;Kdep]^T partials + row norms ----------------
__global__ void __launch_bounds__(256) attn_scores()
{
    int slab = blockIdx.x;      // 0..7
    int bh   = blockIdx.y;      // 0..63
    int b = bh >> 2, h = bh & 3;
    __shared__ unsigned Qh[8][72],  Ql[8][72];    // [kp][c] split
    __shared__ unsigned Kh[8][136];               // [kp][dd] single
    int tid = threadIdx.x;
    int lane = tid & 31, wid = tid >> 5;
    int g = lane >> 2, l4 = lane & 3;
    int wm = wid >> 2, wn = wid & 3;

    int sc  = tid >> 2;
    int kf  = (tid & 3) << 2;
    int kp  = kf >> 1;
    const float* Qp  = g_q  + ((long)b*256 + h*64 + sc) * HWn + kf;
    const float* Kp0 = g_kv + ((long)b*512       + h*64 + sc) * HWn + kf;
    const float* Kp1 = g_kv + ((long)(b+16)*512  + h*64 + sc) * HWn + kf;

    float acc[2][4][4];
    #pragma unroll
    for (int i = 0; i < 2; i++)
        #pragma unroll
        for (int j = 0; j < 4; j++)
            #pragma unroll
            for (int r = 0; r < 4; r++) acc[i][j][r] = 0.f;
    float qn = 0.f, kn0 = 0.f, kn1 = 0.f;
    int n0 = slab * 512;

    for (int nc = n0; nc < n0 + 512; nc += 16) {
        {
            float4 v = *(const float4*)(Qp + nc);
            qn += v.x*v.x + v.y*v.y + v.z*v.z + v.w*v.w;
            unsigned h0,l0,h1,l1;
            split2h(v.x,v.y,h0,l0); split2h(v.z,v.w,h1,l1);
            Qh[kp][sc]=h0; Ql[kp][sc]=l0; Qh[kp+1][sc]=h1; Ql[kp+1][sc]=l1;
        }
        {
            float4 v = *(const float4*)(Kp0 + nc);
            kn0 += v.x*v.x + v.y*v.y + v.z*v.z + v.w*v.w;
            Kh[kp][sc]   = pack2h(v.x, v.y);
            Kh[kp+1][sc] = pack2h(v.z, v.w);
        }
        {
            float4 v = *(const float4*)(Kp1 + nc);
            kn1 += v.x*v.x + v.y*v.y + v.z*v.z + v.w*v.w;
            Kh[kp][sc+64]   = pack2h(v.x, v.y);
            Kh[kp+1][sc+64] = pack2h(v.z, v.w);
        }
        __syncthreads();
        unsigned a_h[2][4], a_l[2][4];
        #pragma unroll
        for (int i = 0; i < 2; i++) {
            int row = wm*32 + i*16 + g;
            a_h[i][0]=Qh[l4][row];   a_h[i][1]=Qh[l4][row+8];
            a_h[i][2]=Qh[l4+4][row]; a_h[i][3]=Qh[l4+4][row+8];
            a_l[i][0]=Ql[l4][row];   a_l[i][1]=Ql[l4][row+8];
            a_l[i][2]=Ql[l4+4][row]; a_l[i][3]=Ql[l4+4][row+8];
        }
        #pragma unroll
        for (int j = 0; j < 4; j++) {
            int col = wn*32 + j*8 + g;
            unsigned bh0=Kh[l4][col], bh1=Kh[l4+4][col];
            #pragma unroll
            for (int i = 0; i < 2; i++) {
                mma_f16(acc[i][j], a_h[i], bh0, bh1);
                mma_f16(acc[i][j], a_l[i], bh0, bh1);
            }
        }
        __syncthreads();
    }
    long base = (long)slab*64 + bh;
    float* Sp = g_S + base*64*128;
    #pragma unroll
    for (int i = 0; i < 2; i++)
        #pragma unroll
        for (int h2 = 0; h2 < 2; h2++) {
            int row = wm*32 + i*16 + g + h2*8;
            #pragma unroll
            for (int j = 0; j < 4; j++) {
                int col = wn*32 + j*8 + 2*l4;
                *(float2*)&Sp[row*128 + col] = make_float2(acc[i][j][h2*2], acc[i][j][h2*2+1]);
            }
        }
    qn  += __shfl_xor_sync(0xffffffffu, qn, 1);  qn  += __shfl_xor_sync(0xffffffffu, qn, 2);
    kn0 += __shfl_xor_sync(0xffffffffu, kn0, 1); kn0 += __shfl_xor_sync(0xffffffffu, kn0, 2);
    kn1 += __shfl_xor_sync(0xffffffffu, kn1, 1); kn1 += __shfl_xor_sync(0xffffffffu, kn1, 2);
    if ((tid & 3) == 0) {
        g_qn2[base*64  + sc]      = qn;
        g_kn2[base*128 + sc]      = kn0;
        g_kn2[base*128 + sc + 64] = kn1;
    }
}

// ---------------- attention A2: combine partials, normalize, softmax, fold gate ----------------
__global__ void __launch_bounds__(128) attn_softmax(const float* __restrict__ attn_scale)
{
    int bh = blockIdx.x; int h = bh & 3;
    __shared__ float qn[64], kn[128];
    int tid = threadIdx.x;
    if (tid < 64) {
        float s = 0.f;
        for (int sl = 0; sl < NSPL; sl++) s += g_qn2[((long)sl*64 + bh)*64 + tid];
        qn[tid] = fmaxf(sqrtf(s), 1e-12f);
    }
    {
        float s = 0.f;
        for (int sl = 0; sl < NSPL; sl++) s += g_kn2[((long)sl*64 + bh)*128 + tid];
        kn[tid] = fmaxf(sqrtf(s), 1e-12f);
    }
    __syncthreads();
    int c = tid & 63, half = tid >> 6;
    float v[64];
    const float* Sp = g_S + (long)bh*64*128 + c*128 + half*64;
    float iq = 1.0f / qn[c];
    #pragma unroll
    for (int d = 0; d < 64; d++) {
        float s = 0.f;
        for (int sl = 0; sl < NSPL; sl++) s += Sp[(long)sl*64*64*128 + d];
        v[d] = s * iq / kn[half*64 + d];
    }
    float mx = -1e30f;
    #pragma unroll
    for (int d = 0; d < 64; d++) mx = fmaxf(mx, v[d]);
    float sum = 0.f;
    #pragma unroll
    for (int d = 0; d < 64; d++) { v[d] = expf(v[d] - mx); sum += v[d]; }
    float gg  = 1.0f / (1.0f + expf(-attn_scale[h]));
    float fac = (half == 0 ? gg : 1.0f - gg) / sum;
    float* P = g_P + (long)bh*64*128 + c*128 + half*64;
    #pragma unroll
    for (int d = 0; d < 64; d++) P[d] = v[d] * fac;
}

// ---------------- attention A3: O = P_comb(64x128) * [Vtex;Vdep](128xHW) ----------------
__global__ void __launch_bounds__(256) attn_pv()
{
    int nt = blockIdx.x;   // 0..31 (128 cols each)
    int bh = blockIdx.y;
    int b = bh >> 2, h = bh & 3;
    __shared__ unsigned Ph[64][72], Pl[64][72];   // all 64 k-pairs of P (split)
    __shared__ unsigned Vh[8][136];               // one 16-dd chunk of V (single)
    int tid = threadIdx.x;
    int lane = tid & 31, wid = tid >> 5;
    int g = lane >> 2, l4 = lane & 3;
    int wm = wid >> 2, wn = wid & 3;

    const float* P = g_P + (long)bh*64*128;
    #pragma unroll
    for (int q = 0; q < 8; q++) {
        int qi = tid + 256*q;
        int c  = qi & 63;
        int df = (qi >> 6) << 2;
        float4 v = *(const float4*)(P + c*128 + df);
        unsigned h0,l0,h1,l1;
        split2h(v.x,v.y,h0,l0); split2h(v.z,v.w,h1,l1);
        int kp = df >> 1;
        Ph[kp][c]=h0; Pl[kp][c]=l0; Ph[kp+1][c]=h1; Pl[kp+1][c]=l1;
    }
    int vkp = tid >> 5, vng = (tid & 31) << 2;
    int n0 = nt * 128;
    float acc[2][4][4];
    #pragma unroll
    for (int i = 0; i < 2; i++)
        #pragma unroll
        for (int j = 0; j < 4; j++)
            #pragma unroll
            for (int r = 0; r < 4; r++) acc[i][j][r] = 0.f;
    __syncthreads();

    for (int d0 = 0; d0 < 128; d0 += 16) {
        int dd = d0 + 2*vkp;
        const float* vp = (dd < 64)
            ? g_kv + ((long)b*512      + 256 + h*64 + dd       )*HWn
            : g_kv + ((long)(b+16)*512 + 256 + h*64 + (dd - 64))*HWn;
        float4 r0 = *(const float4*)(vp + n0 + vng);
        float4 r1 = *(const float4*)(vp + HWn + n0 + vng);
        *(uint4*)&Vh[vkp][vng] = make_uint4(
            pack2h(r0.x, r1.x), pack2h(r0.y, r1.y),
            pack2h(r0.z, r1.z), pack2h(r0.w, r1.w));
        __syncthreads();
        int kb = d0 >> 1;
        unsigned a_h[2][4], a_l[2][4];
        #pragma unroll
        for (int i = 0; i < 2; i++) {
            int row = wm*32 + i*16 + g;
            a_h[i][0]=Ph[kb+l4][row];   a_h[i][1]=Ph[kb+l4][row+8];
            a_h[i][2]=Ph[kb+l4+4][row]; a_h[i][3]=Ph[kb+l4+4][row+8];
            a_l[i][0]=Pl[kb+l4][row];   a_l[i][1]=Pl[kb+l4][row+8];
            a_l[i][2]=Pl[kb+l4+4][row]; a_l[i][3]=Pl[kb+l4+4][row+8];
        }
        #pragma unroll
        for (int j = 0; j < 4; j++) {
            int col = wn*32 + j*8 + g;
            unsigned bh0=Vh[l4][col], bh1=Vh[l4+4][col];
            #pragma unroll
            for (int i = 0; i < 2; i++) {
                mma_f16(acc[i][j], a_h[i], bh0, bh1);
                mma_f16(acc[i][j], a_l[i], bh0, bh1);
            }
        }
        __syncthreads();
    }
    float* O = g_attn + ((long)b*256 + h*64) * HWn;
    #pragma unroll
    for (int i = 0; i < 2; i++)
        #pragma unroll
        for (int h2 = 0; h2 < 2; h2++) {
            int row = wm*32 + i*16 + g + h2*8;
            #pragma unroll
            for (int j = 0; j < 4; j++) {
                int col = wn*32 + j*8 + 2*l4;
                *(float2*)(O + (long)row*HWn + n0 + col) =
                    make_float2(acc[i][j][h2*2], acc[i][j][h2*2+1]);
            }
        }
}

// ---------------- depthwise 3x3 SAME + exact GELU ----------------
__global__ void dwconv_gelu(const float* __restrict__ dww)
{
    int bc = blockIdx.x;
    int c  = bc & 255;
    int hh = blockIdx.y * 4 + threadIdx.y;
    int tx = threadIdx.x;
    const float* in = g_y1 + (long)bc * HWn;
    float s = 0.f;
    #pragma unroll
    for (int di = -1; di <= 1; di++) {
        int hi = hh + di;
        if (hi < 0 || hi > 63) continue;
        #pragma unroll
        for (int dj = -1; dj <= 1; dj++) {
            int wj = tx + dj;
            if (wj < 0 || wj > 63) continue;
            s = fmaf(in[hi*64 + wj], dww[c*9 + (di+1)*3 + (dj+1)], s);
        }
    }
    float g = 0.5f * s * (1.0f + erff(s * 0.70710678118654752f));
    g_y2[(long)bc * HWn + hh*64 + tx] = g;
}

// ---------------- launch ----------------
extern "C" void kernel_launch(void* const* d_in, const int* in_sizes, int n_in,
                              void* d_out, int out_size)
{
    const float* img    = (const float*)d_in[0];
    const float* tex    = (const float*)d_in[1];
    const float* dep    = (const float*)d_in[2];
    const float* qnw    = (const float*)d_in[3];
    const float* qnb    = (const float*)d_in[4];
    const float* kvnw   = (const float*)d_in[5];
    const float* kvnb   = (const float*)d_in[6];
    const float* ascale = (const float*)d_in[7];
    const float* qpw    = (const float*)d_in[8];
    const float* kvpw   = (const float*)d_in[9];
    const float* opw    = (const float*)d_in[10];
    const float* opb    = (const float*)d_in[11];
    const float* fnw    = (const float*)d_in[12];
    const float* fnb    = (const float*)d_in[13];
    const float* f1w    = (const float*)d_in[14];
    const float* dww    = (const float*)d_in[15];
    const float* f2w    = (const float*)d_in[16];
    float* outp = (float*)d_out;

    float *p_q,*p_kv,*p_attn,*p_x,*p_y1,*p_y2;
    float *p_Sq,*p_Bq,*p_Skv,*p_Bkv,*p_Sf1,*p_Bf1;
    cudaGetSymbolAddress((void**)&p_q,    g_q);
    cudaGetSymbolAddress((void**)&p_kv,   g_kv);
    cudaGetSymbolAddress((void**)&p_attn, g_attn);
    cudaGetSymbolAddress((void**)&p_x,    g_x);
    cudaGetSymbolAddress((void**)&p_y1,   g_y1);
    cudaGetSymbolAddress((void**)&p_y2,   g_y2);
    cudaGetSymbolAddress((void**)&p_Sq,   g_Sq);
    cudaGetSymbolAddress((void**)&p_Bq,   g_Bq);
    cudaGetSymbolAddress((void**)&p_Skv,  g_Skv);
    cudaGetSymbolAddress((void**)&p_Bkv,  g_Bkv);
    cudaGetSymbolAddress((void**)&p_Sf1,  g_Sf1);
    cudaGetSymbolAddress((void**)&p_Bf1,  g_Bf1);

    // 0) fold LN weights + pre-split all 5 weight matrices
    prep_w<<<1536, 256>>>(qpw,qnw,qnb, kvpw,kvnw,kvnb, f1w,fnw,fnb, opw, f2w);
    // 1) q = Wq' @ img  (LN stats fused + folded in epilogue)
    gemm_tc<<<dim3(32,2,16), 256>>>(0, img, img, 99, CHW, p_q, CHW,
                                    1, p_Sq, p_Bq, nullptr, nullptr, 0);
    // 2) kv = Wkv' @ [tex;dep]
    gemm_tc<<<dim3(32,4,32), 256>>>(256, tex, dep, 16, CHW, p_kv, 512L*HWn,
                                    1, p_Skv, p_Bkv, nullptr, nullptr, 0);
    // 3) attention
    attn_scores <<<dim3(NSPL,64), 256>>>();
    attn_softmax<<<64, 128>>>(ascale);
    attn_pv     <<<dim3(32,64), 256>>>();
    // 4) x = img + Wo @ attn + bias
    gemm_tc<<<dim3(32,2,16), 256>>>(1024, p_attn, p_attn, 99, CHW, p_x, CHW,
                                    0, nullptr, nullptr, opb, img, CHW);
    // 5) y1 = Wf1' @ LN(x)   (LN stats fused)
    gemm_tc<<<dim3(32,2,16), 256>>>(768, p_x, p_x, 99, CHW, p_y1, CHW,
                                    1, p_Sf1, p_Bf1, nullptr, nullptr, 0);
    dwconv_gelu<<<dim3(4096,16), dim3(64,4)>>>(dww);
    // 6) out = x + fc2 @ y2
    gemm_tc<<<dim3(32,2,16), 256>>>(1280, p_y2, p_y2, 99, CHW, outp, CHW,
                                    0, nullptr, nullptr, nullptr, p_x, CHW);
}